// round 3
// baseline (speedup 1.0000x reference)
#include <cuda_runtime.h>
#include <math_constants.h>

// Chamfer distance, B=16 events, P=Q=4096, 3D.
// R3: candidate-split x4 for occupancy (1024 blocks, 4096 warps),
// partial per-row mins to global scratch, L2-resident combine kernel.

#define NB 16
#define NP 4096
#define THREADS 128
#define RPT 4
#define ROWS (THREADS * RPT)          // 512 query rows per block
#define CHUNKS (NP / ROWS)            // 8
#define CSPLIT 4
#define TQ (NP / CSPLIT)              // 1024 candidates per block (16KB)
#define NROWS (2 * NB * NP)           // 131072 query rows total (both dirs)

#define THREADS2 256
#define BLOCKS2 128
#define ROWS_PER_BLOCK2 (NROWS / BLOCKS2)   // 1024
#define ROWS_PER_THREAD2 (ROWS_PER_BLOCK2 / THREADS2)  // 4

__device__ float g_pmin[CSPLIT * NROWS];   // 2 MB scratch (xn + partial min)
__device__ float g_part2[BLOCKS2];
__device__ unsigned int g_sync2;           // zero-init; reset by last block

typedef unsigned long long u64;

__device__ __forceinline__ u64 pack2(float lo, float hi) {
    u64 r;
    asm("mov.b64 %0, {%1, %2};" : "=l"(r) : "f"(lo), "f"(hi));
    return r;
}
__device__ __forceinline__ u64 ffma2(u64 a, u64 b, u64 c) {
    u64 r;
    asm("fma.rn.f32x2 %0, %1, %2, %3;" : "=l"(r) : "l"(a), "l"(b), "l"(c));
    return r;
}
__device__ __forceinline__ void unpack2(u64 v, float& lo, float& hi) {
    asm("mov.b64 {%0, %1}, %2;" : "=f"(lo), "=f"(hi) : "l"(v));
}

__global__ __launch_bounds__(THREADS)
void chamfer_kernel(const float* __restrict__ gen,
                    const float* __restrict__ label) {
    // Candidate quad per pair j: {(-2x0,-2x1),(-2y0,-2y1),(-2z0,-2z1),(n0,n1)}
    __shared__ __align__(16) float tile[TQ / 2][8];   // 16 KB

    const int dir   = blockIdx.z;                 // 0: gen->gt, 1: gt->gen
    const int b     = blockIdx.y;
    const int chunk = blockIdx.x / CSPLIT;
    const int split = blockIdx.x % CSPLIT;
    const int t     = threadIdx.x;

    const float inv128 = 1.0f / 128.0f;

    // ---- query rows, register resident ----
    u64 xp0[RPT], xp1[RPT], xp2[RPT];
    float xn[RPT], mlo[RPT], mhi[RPT];
#pragma unroll
    for (int r = 0; r < RPT; r++) {
        int row = b * NP + chunk * ROWS + r * THREADS + t;
        float px, py, pz;
        if (dir == 0) {
            const float* s = gen + (size_t)row * 3;
            px = s[0]; py = s[1]; pz = s[2];
        } else {
            const float* s = label + (size_t)row * 5 + 1;
            px = (s[0] - 128.0f) * inv128;
            py = (s[1] - 128.0f) * inv128;
            pz = (s[2] - 128.0f) * inv128;
        }
        xn[r] = px * px + py * py + pz * pz;
        xp0[r] = pack2(px, px);
        xp1[r] = pack2(py, py);
        xp2[r] = pack2(pz, pz);
        mlo[r] = CUDART_INF_F;
        mhi[r] = CUDART_INF_F;
    }

    // ---- load this block's candidate slice into smem ----
#pragma unroll
    for (int p = t; p < TQ; p += THREADS) {
        int idx = b * NP + split * TQ + p;
        float cx, cy, cz;
        if (dir == 0) {
            const float* s = label + (size_t)idx * 5 + 1;
            cx = (s[0] - 128.0f) * inv128;
            cy = (s[1] - 128.0f) * inv128;
            cz = (s[2] - 128.0f) * inv128;
        } else {
            const float* s = gen + (size_t)idx * 3;
            cx = s[0]; cy = s[1]; cz = s[2];
        }
        int j = p >> 1, h = p & 1;
        tile[j][0 + h] = -2.0f * cx;
        tile[j][2 + h] = -2.0f * cy;
        tile[j][4 + h] = -2.0f * cz;
        tile[j][6 + h] = cx * cx + cy * cy + cz * cz;
    }
    __syncthreads();

    const ulonglong2* tp = (const ulonglong2*)tile;

#pragma unroll 8
    for (int j = 0; j < TQ / 2; j++) {
        ulonglong2 c0 = tp[j * 2 + 0];   // {ax, ay}
        ulonglong2 c1 = tp[j * 2 + 1];   // {az, an}
#pragma unroll
        for (int r = 0; r < RPT; r++) {
            u64 d = ffma2(xp2[r], c1.x,
                    ffma2(xp1[r], c0.y,
                    ffma2(xp0[r], c0.x, c1.y)));
            float lo, hi;
            unpack2(d, lo, hi);
            mlo[r] = fminf(mlo[r], lo);
            mhi[r] = fminf(mhi[r], hi);
        }
    }

    // ---- write partial per-row min (xn folded in) ----
#pragma unroll
    for (int r = 0; r < RPT; r++) {
        int row_lin = (dir * NB + b) * NP + chunk * ROWS + r * THREADS + t;
        g_pmin[split * NROWS + row_lin] = xn[r] + fminf(mlo[r], mhi[r]);
    }
}

__global__ __launch_bounds__(THREADS2)
void combine_kernel(float* __restrict__ out) {
    __shared__ float red[THREADS2 / 32];
    __shared__ unsigned int is_last;
    const int t = threadIdx.x;
    const int blk = blockIdx.x;

    float s = 0.0f;
#pragma unroll
    for (int i = 0; i < ROWS_PER_THREAD2; i++) {
        int row = blk * ROWS_PER_BLOCK2 + i * THREADS2 + t;
        float m = __ldcg(&g_pmin[row]);
#pragma unroll
        for (int sp = 1; sp < CSPLIT; sp++)
            m = fminf(m, __ldcg(&g_pmin[sp * NROWS + row]));
        s += m;
    }

#pragma unroll
    for (int o = 16; o > 0; o >>= 1)
        s += __shfl_down_sync(0xffffffffu, s, o);
    if ((t & 31) == 0) red[t >> 5] = s;
    __syncthreads();
    if (t == 0) {
        float tot = 0.0f;
#pragma unroll
        for (int w = 0; w < THREADS2 / 32; w++) tot += red[w];
        g_part2[blk] = tot;
        __threadfence();
        unsigned int v = atomicAdd(&g_sync2, 1u);
        is_last = (v == (unsigned int)(BLOCKS2 - 1)) ? 1u : 0u;
    }
    __syncthreads();

    if (is_last) {
        __threadfence();
        float ps = (t < BLOCKS2) ? __ldcg(&g_part2[t]) : 0.0f;
#pragma unroll
        for (int o = 16; o > 0; o >>= 1)
            ps += __shfl_down_sync(0xffffffffu, ps, o);
        if ((t & 31) == 0) red[t >> 5] = ps;
        __syncthreads();
        if (t == 0) {
            float tot = 0.0f;
#pragma unroll
            for (int w = 0; w < THREADS2 / 32; w++) tot += red[w];
            out[0] = tot * (1.0f / 65536.0f);   // / (P * B)
            g_sync2 = 0u;                       // reset for next call
        }
    }
}

extern "C" void kernel_launch(void* const* d_in, const int* in_sizes, int n_in,
                              void* d_out, int out_size) {
    const float* gen   = (const float*)d_in[0];  // [B*P, 3]
    // d_in[1] = batch_gen (int32), unused: contiguous equal segments
    const float* label = (const float*)d_in[2];  // [B*Q, 5]
    float* out = (float*)d_out;

    dim3 grid(CHUNKS * CSPLIT, NB, 2);
    chamfer_kernel<<<grid, THREADS>>>(gen, label);
    combine_kernel<<<BLOCKS2, THREADS2>>>(out);
}

// round 4
// speedup vs baseline: 1.3369x; 1.3369x over previous
#include <cuda_runtime.h>
#include <math_constants.h>

// Chamfer distance, B=16 events, P=Q=4096, 3D.
// R4 = R2 shape (256 blocks, whole-event 2-pass candidate sweep, fused
// deterministic finalize) with one change: 256 threads/block (RPT=2)
// to raise warps/SM from ~7 to ~16.

#define NB 16
#define NP 4096
#define THREADS 256
#define RPT 2
#define ROWS (THREADS * RPT)          // 512 query rows per block
#define CHUNKS (NP / ROWS)            // 8
#define TQ 2048                       // candidates per smem pass (32KB)
#define NPASS (NP / TQ)               // 2
#define NPART (CHUNKS * NB * 2)       // 256 partial sums

__device__ float g_partials[NPART];
__device__ unsigned int g_sync;       // zero-init; reset by last block each call

typedef unsigned long long u64;

__device__ __forceinline__ u64 pack2(float lo, float hi) {
    u64 r;
    asm("mov.b64 %0, {%1, %2};" : "=l"(r) : "f"(lo), "f"(hi));
    return r;
}
__device__ __forceinline__ u64 ffma2(u64 a, u64 b, u64 c) {
    u64 r;
    asm("fma.rn.f32x2 %0, %1, %2, %3;" : "=l"(r) : "l"(a), "l"(b), "l"(c));
    return r;
}
__device__ __forceinline__ void unpack2(u64 v, float& lo, float& hi) {
    asm("mov.b64 {%0, %1}, %2;" : "=f"(lo), "=f"(hi) : "l"(v));
}

__global__ __launch_bounds__(THREADS)
void chamfer_kernel(const float* __restrict__ gen,
                    const float* __restrict__ label,
                    float* __restrict__ out) {
    // Candidate quad per pair j: {(-2x0,-2x1),(-2y0,-2y1),(-2z0,-2z1),(n0,n1)}
    __shared__ __align__(16) float tile[TQ / 2][8];   // 32 KB
    __shared__ float red[THREADS / 32];
    __shared__ unsigned int is_last;

    const int dir   = blockIdx.z;   // 0: gen->gt, 1: gt->gen
    const int b     = blockIdx.y;
    const int chunk = blockIdx.x;
    const int t     = threadIdx.x;

    const float inv128 = 1.0f / 128.0f;

    // ---- query rows, register resident ----
    u64 xp0[RPT], xp1[RPT], xp2[RPT];
    float xn[RPT], mlo[RPT], mhi[RPT];
#pragma unroll
    for (int r = 0; r < RPT; r++) {
        int row = b * NP + chunk * ROWS + r * THREADS + t;
        float px, py, pz;
        if (dir == 0) {
            const float* s = gen + (size_t)row * 3;
            px = s[0]; py = s[1]; pz = s[2];
        } else {
            const float* s = label + (size_t)row * 5 + 1;
            px = (s[0] - 128.0f) * inv128;
            py = (s[1] - 128.0f) * inv128;
            pz = (s[2] - 128.0f) * inv128;
        }
        xn[r] = px * px + py * py + pz * pz;
        xp0[r] = pack2(px, px);
        xp1[r] = pack2(py, py);
        xp2[r] = pack2(pz, pz);
        mlo[r] = CUDART_INF_F;
        mhi[r] = CUDART_INF_F;
    }

    // ---- sweep candidates in NPASS big passes ----
    for (int pass = 0; pass < NPASS; pass++) {
        __syncthreads();
#pragma unroll
        for (int p = t; p < TQ; p += THREADS) {
            int idx = b * NP + pass * TQ + p;
            float cx, cy, cz;
            if (dir == 0) {
                const float* s = label + (size_t)idx * 5 + 1;
                cx = (s[0] - 128.0f) * inv128;
                cy = (s[1] - 128.0f) * inv128;
                cz = (s[2] - 128.0f) * inv128;
            } else {
                const float* s = gen + (size_t)idx * 3;
                cx = s[0]; cy = s[1]; cz = s[2];
            }
            int j = p >> 1, h = p & 1;
            tile[j][0 + h] = -2.0f * cx;
            tile[j][2 + h] = -2.0f * cy;
            tile[j][4 + h] = -2.0f * cz;
            tile[j][6 + h] = cx * cx + cy * cy + cz * cz;
        }
        __syncthreads();

        const ulonglong2* tp = (const ulonglong2*)tile;

#pragma unroll 8
        for (int j = 0; j < TQ / 2; j++) {
            ulonglong2 c0 = tp[j * 2 + 0];   // {ax, ay}
            ulonglong2 c1 = tp[j * 2 + 1];   // {az, an}
#pragma unroll
            for (int r = 0; r < RPT; r++) {
                u64 d = ffma2(xp2[r], c1.x,
                        ffma2(xp1[r], c0.y,
                        ffma2(xp0[r], c0.x, c1.y)));
                float lo, hi;
                unpack2(d, lo, hi);
                mlo[r] = fminf(mlo[r], lo);
                mhi[r] = fminf(mhi[r], hi);
            }
        }
    }

    // ---- per-thread finalize: min d = x^2 + min(d') ----
    float s = 0.0f;
#pragma unroll
    for (int r = 0; r < RPT; r++)
        s += fminf(mlo[r], mhi[r]) + xn[r];

    // ---- deterministic block reduction ----
#pragma unroll
    for (int o = 16; o > 0; o >>= 1)
        s += __shfl_down_sync(0xffffffffu, s, o);
    if ((t & 31) == 0) red[t >> 5] = s;
    __syncthreads();
    if (t == 0) {
        float tot = 0.0f;
#pragma unroll
        for (int w = 0; w < THREADS / 32; w++) tot += red[w];
        int lin = (blockIdx.z * gridDim.y + blockIdx.y) * gridDim.x + blockIdx.x;
        g_partials[lin] = tot;
        __threadfence();
        unsigned int v = atomicAdd(&g_sync, 1u);
        is_last = (v == (unsigned int)(NPART - 1)) ? 1u : 0u;
    }
    __syncthreads();

    // ---- last block: fixed-order global reduction (deterministic) ----
    if (is_last) {
        __threadfence();
        float ps = __ldcg(&g_partials[t]);   // NPART == THREADS == 256
#pragma unroll
        for (int o = 16; o > 0; o >>= 1)
            ps += __shfl_down_sync(0xffffffffu, ps, o);
        if ((t & 31) == 0) red[t >> 5] = ps;
        __syncthreads();
        if (t == 0) {
            float tot = 0.0f;
#pragma unroll
            for (int w = 0; w < THREADS / 32; w++) tot += red[w];
            out[0] = tot * (1.0f / 65536.0f);   // / (P * B)
            g_sync = 0u;                        // reset for next call
        }
    }
}

extern "C" void kernel_launch(void* const* d_in, const int* in_sizes, int n_in,
                              void* d_out, int out_size) {
    const float* gen   = (const float*)d_in[0];  // [B*P, 3]
    // d_in[1] = batch_gen (int32), unused: contiguous equal segments
    const float* label = (const float*)d_in[2];  // [B*Q, 5]
    float* out = (float*)d_out;

    dim3 grid(CHUNKS, NB, 2);
    chamfer_kernel<<<grid, THREADS>>>(gen, label, out);
}

// round 6
// speedup vs baseline: 1.4299x; 1.0696x over previous
#include <cuda_runtime.h>
#include <math_constants.h>

// Chamfer distance, B=16 events, P=Q=4096, 3D.
// R6 = R4 shape (256 blocks x 256 thr, 2-pass sweep, fused finalize) +
// software-pipelined candidate prefetch (hide LDS 29-cyc latency).
// (min.f32x2 from R5 doesn't exist in PTX; scalar FMNMX on aliased halves.)

#define NB 16
#define NP 4096
#define THREADS 256
#define RPT 2
#define ROWS (THREADS * RPT)          // 512 query rows per block
#define CHUNKS (NP / ROWS)            // 8
#define TQ 2048                       // candidates per smem pass (32KB)
#define NPASS (NP / TQ)               // 2
#define NPART (CHUNKS * NB * 2)       // 256 partial sums

__device__ float g_partials[NPART];
__device__ unsigned int g_sync;       // zero-init; reset by last block each call

typedef unsigned long long u64;

__device__ __forceinline__ u64 pack2(float lo, float hi) {
    u64 r;
    asm("mov.b64 %0, {%1, %2};" : "=l"(r) : "f"(lo), "f"(hi));
    return r;
}
__device__ __forceinline__ u64 ffma2(u64 a, u64 b, u64 c) {
    u64 r;
    asm("fma.rn.f32x2 %0, %1, %2, %3;" : "=l"(r) : "l"(a), "l"(b), "l"(c));
    return r;
}
__device__ __forceinline__ void unpack2(u64 v, float& lo, float& hi) {
    asm("mov.b64 {%0, %1}, %2;" : "=f"(lo), "=f"(hi) : "l"(v));
}

__global__ __launch_bounds__(THREADS)
void chamfer_kernel(const float* __restrict__ gen,
                    const float* __restrict__ label,
                    float* __restrict__ out) {
    // Candidate quad per pair j: {(-2x0,-2x1),(-2y0,-2y1),(-2z0,-2z1),(n0,n1)}
    // +1 pad quad so the pipelined prefetch can read one past the end.
    __shared__ __align__(16) float tile[TQ / 2 + 1][8];   // 32KB + 32B
    __shared__ float red[THREADS / 32];
    __shared__ unsigned int is_last;

    const int dir   = blockIdx.z;   // 0: gen->gt, 1: gt->gen
    const int b     = blockIdx.y;
    const int chunk = blockIdx.x;
    const int t     = threadIdx.x;

    const float inv128 = 1.0f / 128.0f;

    // ---- query rows, register resident ----
    u64 xp0[RPT], xp1[RPT], xp2[RPT];
    float xn[RPT], mlo[RPT], mhi[RPT];
#pragma unroll
    for (int r = 0; r < RPT; r++) {
        int row = b * NP + chunk * ROWS + r * THREADS + t;
        float px, py, pz;
        if (dir == 0) {
            const float* s = gen + (size_t)row * 3;
            px = s[0]; py = s[1]; pz = s[2];
        } else {
            const float* s = label + (size_t)row * 5 + 1;
            px = (s[0] - 128.0f) * inv128;
            py = (s[1] - 128.0f) * inv128;
            pz = (s[2] - 128.0f) * inv128;
        }
        xn[r] = px * px + py * py + pz * pz;
        xp0[r] = pack2(px, px);
        xp1[r] = pack2(py, py);
        xp2[r] = pack2(pz, pz);
        mlo[r] = CUDART_INF_F;
        mhi[r] = CUDART_INF_F;
    }

    // ---- sweep candidates in NPASS big passes ----
    for (int pass = 0; pass < NPASS; pass++) {
        __syncthreads();
#pragma unroll
        for (int p = t; p < TQ; p += THREADS) {
            int idx = b * NP + pass * TQ + p;
            float cx, cy, cz;
            if (dir == 0) {
                const float* s = label + (size_t)idx * 5 + 1;
                cx = (s[0] - 128.0f) * inv128;
                cy = (s[1] - 128.0f) * inv128;
                cz = (s[2] - 128.0f) * inv128;
            } else {
                const float* s = gen + (size_t)idx * 3;
                cx = s[0]; cy = s[1]; cz = s[2];
            }
            int j = p >> 1, h = p & 1;
            tile[j][0 + h] = -2.0f * cx;
            tile[j][2 + h] = -2.0f * cy;
            tile[j][4 + h] = -2.0f * cz;
            tile[j][6 + h] = cx * cx + cy * cy + cz * cz;
        }
        __syncthreads();

        const ulonglong2* tp = (const ulonglong2*)tile;

        // software pipeline: prefetch next iter's quad while computing current
        ulonglong2 c0 = tp[0];
        ulonglong2 c1 = tp[1];
#pragma unroll 8
        for (int j = 0; j < TQ / 2; j++) {
            ulonglong2 n0 = tp[j * 2 + 2];   // last iter reads the pad quad
            ulonglong2 n1 = tp[j * 2 + 3];
#pragma unroll
            for (int r = 0; r < RPT; r++) {
                u64 d = ffma2(xp2[r], c1.x,
                        ffma2(xp1[r], c0.y,
                        ffma2(xp0[r], c0.x, c1.y)));
                float lo, hi;
                unpack2(d, lo, hi);
                mlo[r] = fminf(mlo[r], lo);
                mhi[r] = fminf(mhi[r], hi);
            }
            c0 = n0;
            c1 = n1;
        }
    }

    // ---- per-thread finalize: min d = x^2 + min(d') ----
    float s = 0.0f;
#pragma unroll
    for (int r = 0; r < RPT; r++)
        s += fminf(mlo[r], mhi[r]) + xn[r];

    // ---- deterministic block reduction ----
#pragma unroll
    for (int o = 16; o > 0; o >>= 1)
        s += __shfl_down_sync(0xffffffffu, s, o);
    if ((t & 31) == 0) red[t >> 5] = s;
    __syncthreads();
    if (t == 0) {
        float tot = 0.0f;
#pragma unroll
        for (int w = 0; w < THREADS / 32; w++) tot += red[w];
        int lin = (blockIdx.z * gridDim.y + blockIdx.y) * gridDim.x + blockIdx.x;
        g_partials[lin] = tot;
        __threadfence();
        unsigned int v = atomicAdd(&g_sync, 1u);
        is_last = (v == (unsigned int)(NPART - 1)) ? 1u : 0u;
    }
    __syncthreads();

    // ---- last block: fixed-order global reduction (deterministic) ----
    if (is_last) {
        __threadfence();
        float ps = __ldcg(&g_partials[t]);   // NPART == THREADS == 256
#pragma unroll
        for (int o = 16; o > 0; o >>= 1)
            ps += __shfl_down_sync(0xffffffffu, ps, o);
        if ((t & 31) == 0) red[t >> 5] = ps;
        __syncthreads();
        if (t == 0) {
            float tot = 0.0f;
#pragma unroll
            for (int w = 0; w < THREADS / 32; w++) tot += red[w];
            out[0] = tot * (1.0f / 65536.0f);   // / (P * B)
            g_sync = 0u;                        // reset for next call
        }
    }
}

extern "C" void kernel_launch(void* const* d_in, const int* in_sizes, int n_in,
                              void* d_out, int out_size) {
    const float* gen   = (const float*)d_in[0];  // [B*P, 3]
    // d_in[1] = batch_gen (int32), unused: contiguous equal segments
    const float* label = (const float*)d_in[2];  // [B*Q, 5]
    float* out = (float*)d_out;

    dim3 grid(CHUNKS, NB, 2);
    chamfer_kernel<<<grid, THREADS>>>(gen, label, out);
}